// round 15
// baseline (speedup 1.0000x reference)
#include <cuda_runtime.h>

#define B_      64
#define S_      200
#define DK_     32
#define NQ1     4097
#define NCH64   65            // 64-row chunks per batch (4160 rows padded)
#define NMC     130           // 32-row microchunks per batch
#define NBLK    296           // 148 SMs x 2 CTAs exactly
#define TSTEPS  199
#define RING    4

// g_h layout: [b][microchunk][k=32][r=32], r swizzled: rsw = r ^ (8*(k&3)).
static __device__ float g_h[(size_t)B_ * NMC * 1024];
static __device__ float g_ht[S_ * B_ * DK_];
static __device__ float g_learn[S_ * B_ * DK_];
static __device__ float g_it[S_ * B_ * DK_];
static __device__ int   g_flag[B_];

typedef unsigned long long ull;

__device__ __forceinline__ unsigned smem_u32(const void* p) {
    unsigned a;
    asm("{ .reg .u64 t; cvta.to.shared.u64 t, %1; cvt.u32.u64 %0, t; }" : "=r"(a) : "l"(p));
    return a;
}
__device__ __forceinline__ void bulk_g2s(unsigned sdst, const void* gsrc, unsigned bytes,
                                         unsigned mbar) {
    asm volatile(
        "cp.async.bulk.shared::cta.global.mbarrier::complete_tx::bytes [%0], [%1], %2, [%3];"
        :: "r"(sdst), "l"(gsrc), "r"(bytes), "r"(mbar) : "memory");
}
__device__ __forceinline__ void mbar_wait(unsigned mbar, unsigned phase) {
    asm volatile(
        "{\n\t.reg .pred P;\n\t"
        "W_%=:\n\t"
        "mbarrier.try_wait.parity.shared.b64 P, [%0], %1, 0x989680;\n\t"
        "@P bra D_%=;\n\t"
        "bra.uni W_%=;\n\t"
        "D_%=:\n\t}"
        :: "r"(mbar), "r"(phase) : "memory");
}
__device__ __forceinline__ float tf32hi(float v) {
    return __uint_as_float(__float_as_uint(v) & 0xFFFFE000u);
}
__device__ __forceinline__ void mma8(float* c, const float* a, const float* b) {
    asm("mma.sync.aligned.m16n8k8.row.col.f32.tf32.tf32.f32 "
        "{%0,%1,%2,%3}, {%4,%5,%6,%7}, {%8,%9}, {%0,%1,%2,%3};"
        : "+f"(c[0]), "+f"(c[1]), "+f"(c[2]), "+f"(c[3])
        : "r"(__float_as_uint(a[0])), "r"(__float_as_uint(a[1])),
          "r"(__float_as_uint(a[2])), "r"(__float_as_uint(a[3])),
          "r"(__float_as_uint(b[0])), "r"(__float_as_uint(b[1])));
}

// ---------------------------------------------------------------------------
// K1: init g_h (swizzled, padding zeroed), zero h_tilde, flags, pred[:,0]=0
// ---------------------------------------------------------------------------
__global__ void k_init(const float* __restrict__ h0, float* __restrict__ pred) {
    const int PERB = NMC * 1024;
    int stride = gridDim.x * blockDim.x;
    long total = (long)B_ * PERB;
    for (long i = blockIdx.x * blockDim.x + threadIdx.x; i < total; i += stride) {
        int b = (int)(i / PERB);
        int rem = (int)(i - (long)b * PERB);
        int mc = rem >> 10;
        int kk = (rem & 1023) >> 5;
        int rsw = rem & 31;
        int r = rsw ^ (8 * (kk & 3));
        int grow = mc * 32 + r;
        g_h[i] = (grow < NQ1) ? h0[grow * DK_ + kk] : 0.0f;
    }
    int gid = blockIdx.x * blockDim.x + threadIdx.x;
    for (int i = gid; i < S_ * B_ * DK_; i += stride) g_ht[i] = 0.0f;
    if (gid < B_) { pred[gid * S_] = 0.0f; g_flag[gid] = 0; }
}

// ---------------------------------------------------------------------------
__global__ void k_embed(const int* __restrict__ e_data, const int* __restrict__ at_data,
                        const int* __restrict__ it_data, const float* __restrict__ a_data,
                        const float* __restrict__ E_e, const float* __restrict__ E_at,
                        const float* __restrict__ E_it,
                        const float* __restrict__ W1, const float* __restrict__ b1) {
    int idx = blockIdx.x * blockDim.x + threadIdx.x;
    if (idx >= S_ * B_ * DK_) return;
    int t = idx / (B_ * DK_);
    int rem = idx - t * (B_ * DK_);
    int b = rem >> 5;
    int k = rem & 31;
    int e  = e_data[b * S_ + t];
    int at = at_data[b * S_ + t];
    int it = it_data[b * S_ + t];
    float a = a_data[b * S_ + t];
    const float* ee  = E_e  + e  * DK_;
    const float* eat = E_at + at * DK_;
    const float* w1k = W1 + k * (3 * DK_);
    float s = b1[k];
    float ws = 0.0f;
#pragma unroll
    for (int j = 0; j < DK_; j++) {
        s = fmaf(ee[j],  w1k[j],       s);
        s = fmaf(eat[j], w1k[DK_ + j], s);
        ws += w1k[2 * DK_ + j];
    }
    s = fmaf(a, ws, s);
    g_learn[(t * B_ + b) * DK_ + k] = s;
    g_it[(t * B_ + b) * DK_ + k]    = E_it[it * DK_ + k];
}

// ---------------------------------------------------------------------------
__global__ void k_ht0(const int* __restrict__ e_data, const float* __restrict__ q,
                      const float* __restrict__ h0) {
    int b = blockIdx.x;
    int w = threadIdx.x >> 5;
    int lane = threadIdx.x & 31;
    const float* qr = q + (long)e_data[b * S_] * NQ1;
    float acc = 0.0f;
    for (int n = w; n < NQ1; n += 8) {
        float qv = qr[n];
        if (qv != 0.0f) acc = fmaf(qv, h0[n * DK_ + lane], acc);
    }
    atomicAdd(&g_ht[b * DK_ + lane], acc);
}

// ---------------------------------------------------------------------------
// k_seq: persistent, 296 blocks, 256 thr, 2 CTAs/SM. Warp owns 8 rows per
// 64-row chunk: tf32 mma (3-term hi/lo) + in-warp epilogue, no per-chunk
// block sync. 4-deep TMA ring (prefetch distance 4) hides bulk-copy latency.
// ---------------------------------------------------------------------------
__global__ void __launch_bounds__(256, 2)
k_seq(const int* __restrict__ e_data, const float* __restrict__ q,
      const float* __restrict__ E_e,
      const float* __restrict__ W2, const float* __restrict__ b2,
      const float* __restrict__ W3, const float* __restrict__ b3,
      const float* __restrict__ W4, const float* __restrict__ b4,
      const float* __restrict__ W5, const float* __restrict__ b5,
      float* __restrict__ pred) {
    __shared__ __align__(16) float sh_h[RING][2048];   // 4 x 8KB
    __shared__ __align__(16) float sh_qe[RING][72];
    __shared__ __align__(16) float sh_qn[RING][72];
    __shared__ __align__(8)  ull   sh_mbar[RING];
    __shared__ int   sh_cnt[RING];
    __shared__ float sh_x[4 * DK_];
    __shared__ float sh_LG[DK_];
    __shared__ float sh_cv[DK_];
    __shared__ float sh_gl[DK_];
    __shared__ float sh_cB[DK_];

    const int g = blockIdx.x;
    const int tid = threadIdx.x;
    const int w = tid >> 5;
    const int lane = tid & 31;
    const int g2 = lane >> 2;
    const int tg = lane & 3;

    int b, ib, nb;
    if (g < 200) { b = g / 5; ib = g - b * 5; nb = 5; }
    else { int h2 = g - 200; int bb = h2 >> 2; b = 40 + bb; ib = h2 & 3; nb = 4; }
    const int clo = (ib * NCH64) / nb;
    const int chi = ((ib + 1) * NCH64) / nb;
    const int nch = chi - clo;
    const int total_u = TSTEPS * nch;

    const unsigned mb_full = smem_u32(&sh_mbar[0]);

    if (tid == 0) {
#pragma unroll
        for (int s = 0; s < RING; s++) {
            asm volatile("mbarrier.init.shared.b64 [%0], 1;" :: "r"(mb_full + s * 8));
            sh_cnt[s] = 0;
        }
        asm volatile("fence.proxy.async.shared::cta;" ::: "memory");
    }
    __syncthreads();

#define ISSUE_U(U)                                                                      \
    {                                                                                   \
        int tu = (U) / nch;                                                             \
        int cu = (U) - tu * nch;                                                        \
        int gc = clo + cu;                                                              \
        int rs_ = gc * 64;                                                              \
        int sl_ = (U) & (RING - 1);                                                     \
        unsigned mb = mb_full + sl_ * 8;                                                \
        int etu = e_data[b * S_ + tu];                                                  \
        int enu = e_data[b * S_ + tu + 1];                                              \
        ull pe = (ull)(q + (long)etu * NQ1 + rs_);                                      \
        ull pn = (ull)(q + (long)enu * NQ1 + rs_);                                      \
        unsigned qeb = ((256u + (unsigned)(pe & 15)) + 15) & ~15u;                      \
        unsigned qnb = ((256u + (unsigned)(pn & 15)) + 15) & ~15u;                      \
        asm volatile("mbarrier.arrive.expect_tx.shared.b64 _, [%0], %1;"                \
                     :: "r"(mb), "r"(8192u + qeb + qnb) : "memory");                    \
        bulk_g2s(smem_u32(&sh_h[sl_][0]), g_h + ((size_t)b * NMC + 2 * gc) * 1024,      \
                 8192u, mb);                                                            \
        bulk_g2s(smem_u32(&sh_qe[sl_][0]), (const void*)(pe & ~15ULL), qeb, mb);        \
        bulk_g2s(smem_u32(&sh_qn[sl_][0]), (const void*)(pn & ~15ULL), qnb, mb);        \
    }

    if (tid == 0) { ISSUE_U(0) ISSUE_U(1) ISSUE_U(2) ISSUE_U(3) }

    // ---- W4h fragments (hi/lo), loaded once ----
    float ah[2][4][4], al[2][4][4];
#pragma unroll
    for (int mt = 0; mt < 2; mt++)
#pragma unroll
        for (int kt = 0; kt < 4; kt++) {
            int d0 = g2 + 16 * mt, d1 = d0 + 8;
            int k0 = 8 * kt + tg,  k1 = k0 + 4;
            float v0 = W4[d0 * 96 + k0];
            float v1 = W4[d1 * 96 + k0];
            float v2 = W4[d0 * 96 + k1];
            float v3 = W4[d1 * 96 + k1];
            ah[mt][kt][0] = tf32hi(v0); al[mt][kt][0] = v0 - ah[mt][kt][0];
            ah[mt][kt][1] = tf32hi(v1); al[mt][kt][1] = v1 - ah[mt][kt][1];
            ah[mt][kt][2] = tf32hi(v2); al[mt][kt][2] = v2 - ah[mt][kt][2];
            ah[mt][kt][3] = tf32hi(v3); al[mt][kt][3] = v3 - ah[mt][kt][3];
        }

    // Per-warp constants for its 8-row n-tile
    const int nlo = (8 * w) & 31;                  // row base within microchunk
    const int mcw = w >> 2;                        // microchunk index (0/1)
    const int xr  = (nlo + g2) ^ (8 * tg);         // B-frag swizzled row
    const int rc0 = 8 * w + 2 * tg;                // chunk-row of frag row j=0
    const int xob = 8 * (g2 & 3);
    const int xo0 = (nlo + 2 * tg) ^ xob;          // store/load col for row j0
    const int xo1 = (nlo + 2 * tg + 1) ^ xob;      // ... row j1
    int u = 0;

    for (int t = 0; t < TSTEPS; t++) {
        if (t > 0) {
            if (tid == 0) {
                int need = nb * t;
                int v;
                do {
                    asm volatile("ld.global.acquire.gpu.b32 %0, [%1];"
                                 : "=r"(v) : "l"(&g_flag[b]));
                } while (v < need);
            }
            __syncthreads();
        }

        const int e_t = e_data[b * S_ + t];
        const int e_n = e_data[b * S_ + t + 1];

        // ---- prologue: warps 0 (lg), 1 (gl), 2 (cB); warp 3 y-pred ----
        if (w < 3) {
            if (w == 0) {
                sh_x[lane]           = (t == 0) ? 0.0f : g_learn[((t - 1) * B_ + b) * DK_ + lane];
                sh_x[DK_ + lane]     = g_it[(t * B_ + b) * DK_ + lane];
                sh_x[2 * DK_ + lane] = g_learn[(t * B_ + b) * DK_ + lane];
                sh_x[3 * DK_ + lane] = g_ht[(t * B_ + b) * DK_ + lane];
            }
            asm volatile("bar.sync 7, 96;" ::: "memory");
            float lg = 0.0f;
            if (w == 0) {
                const float4* wk = (const float4*)(W2 + lane * 128);
                const float4* xv4 = (const float4*)sh_x;
                float a0 = b2[lane], a1 = 0.f, a2 = 0.f, a3 = 0.f;
#pragma unroll
                for (int j = 0; j < 32; j++) {
                    float4 xv = xv4[j]; float4 wa = wk[j];
                    a0 = fmaf(xv.x, wa.x, a0); a1 = fmaf(xv.y, wa.y, a1);
                    a2 = fmaf(xv.z, wa.z, a2); a3 = fmaf(xv.w, wa.w, a3);
                }
                lg = (a0 + a1) + (a2 + a3);
            } else if (w == 1) {
                const float4* wk = (const float4*)(W3 + lane * 128);
                const float4* xv4 = (const float4*)sh_x;
                float a0 = b3[lane], a1 = 0.f, a2 = 0.f, a3 = 0.f;
#pragma unroll
                for (int j = 0; j < 32; j++) {
                    float4 xv = xv4[j]; float4 wa = wk[j];
                    a0 = fmaf(xv.x, wa.x, a0); a1 = fmaf(xv.y, wa.y, a1);
                    a2 = fmaf(xv.z, wa.z, a2); a3 = fmaf(xv.w, wa.w, a3);
                }
                float gl = (a0 + a1) + (a2 + a3);
                sh_gl[lane] = 1.0f / (1.0f + expf(-gl));
            } else {
                const float* wk = W4 + lane * (3 * DK_) + 2 * DK_;
                float a0 = b4[lane], a1 = 0.f;
#pragma unroll
                for (int j = 0; j < DK_; j += 2) {
                    a0 = fmaf(sh_x[DK_ + j],     wk[j],     a0);
                    a1 = fmaf(sh_x[DK_ + j + 1], wk[j + 1], a1);
                }
                sh_cB[lane] = a0 + a1;
            }
            asm volatile("bar.sync 7, 96;" ::: "memory");
            if (w == 0) {
                lg = tanhf(lg);
                sh_LG[lane] = sh_gl[lane] * (lg + 1.0f) * 0.5f;
                __syncwarp();
                const float* w4l = W4 + lane * (3 * DK_) + DK_;
                float c0 = sh_cB[lane], c1 = 0.f;
#pragma unroll
                for (int j = 0; j < DK_; j += 2) {
                    c0 = fmaf(sh_LG[j],     w4l[j],     c0);
                    c1 = fmaf(sh_LG[j + 1], w4l[j + 1], c1);
                }
                sh_cv[lane] = c0 + c1;
            }
        } else if (w == 3 && ib == 0 && t > 0) {
            const float* ee = E_e + e_t * DK_;
            const float* ht = g_ht + (t * B_ + b) * DK_;
            const float* w5k = W5 + lane * (2 * DK_);
            float z = b5[lane];
#pragma unroll
            for (int j = 0; j < DK_; j++) {
                z = fmaf(ee[j], w5k[j], z);
                z = fmaf(ht[j], w5k[DK_ + j], z);
            }
            float s = 1.0f / (1.0f + expf(-z));
#pragma unroll
            for (int off = 16; off; off >>= 1)
                s += __shfl_xor_sync(0xffffffffu, s, off);
            if (lane == 0) pred[b * S_ + t] = s * (1.0f / DK_);
        }
        __syncthreads();

        // per-step per-thread constants for its 4 dims
        float cvd[4], LGd[4];
#pragma unroll
        for (int m = 0; m < 4; m++) {
            cvd[m] = sh_cv[g2 + 8 * m];
            LGd[m] = sh_LG[g2 + 8 * m];
        }
        float* htn = g_ht + ((t + 1) * B_ + b) * DK_;

        for (int c = 0; c < nch; c++, u++) {
            const int slot = u & (RING - 1);
            const unsigned phase = (u >> 2) & 1;
            mbar_wait(mb_full + slot * 8, phase);

            const int gc = clo + c;
            const int rs = gc * 64;
            float* tloc = sh_h[slot] + (mcw << 10);

            // ---- B frags + 3-term tf32 mma ----
            float bh[4][2], bl[4][2];
#pragma unroll
            for (int kt = 0; kt < 4; kt++) {
                int k0 = 8 * kt + tg;
                float v0 = tloc[k0 * 32 + xr];
                float v1 = tloc[(k0 + 4) * 32 + xr];
                bh[kt][0] = tf32hi(v0); bl[kt][0] = v0 - bh[kt][0];
                bh[kt][1] = tf32hi(v1); bl[kt][1] = v1 - bh[kt][1];
            }
            float C0[4] = {0.f, 0.f, 0.f, 0.f};
            float C1[4] = {0.f, 0.f, 0.f, 0.f};
#pragma unroll
            for (int kt = 0; kt < 4; kt++) {
                mma8(C0, ah[0][kt], bh[kt]);
                mma8(C1, ah[1][kt], bh[kt]);
            }
#pragma unroll
            for (int kt = 0; kt < 4; kt++) {
                mma8(C0, ah[0][kt], bl[kt]);
                mma8(C1, ah[1][kt], bl[kt]);
            }
#pragma unroll
            for (int kt = 0; kt < 4; kt++) {
                mma8(C0, al[0][kt], bh[kt]);
                mma8(C1, al[1][kt], bh[kt]);
            }

            // ---- in-warp epilogue: this thread's 2 rows x 4 dims ----
            const int qoe = (int)(((ull)(q + (long)e_t * NQ1 + rs) >> 2) & 3);
            const int qon = (int)(((ull)(q + (long)e_n * NQ1 + rs) >> 2) & 3);
            const bool v0ok = (rs + rc0) < NQ1;
            const bool v1ok = (rs + rc0 + 1) < NQ1;
            const float qe0 = v0ok ? sh_qe[slot][qoe + rc0]     : 0.0f;
            const float qe1 = v1ok ? sh_qe[slot][qoe + rc0 + 1] : 0.0f;
            const float qn0 = v0ok ? sh_qn[slot][qon + rc0]     : 0.0f;
            const float qn1 = v1ok ? sh_qn[slot][qon + rc0 + 1] : 0.0f;
            float* gob = g_h + ((size_t)b * NMC + 2 * gc + mcw) * 1024;

#define EPI(Z0, Z1, M)                                                         \
    {                                                                          \
        const int dim = g2 + 8 * (M);                                          \
        float hk0 = tloc[dim * 32 + xo0];                                      \
        float hk1 = tloc[dim * 32 + xo1];                                      \
        float gm0 = __fdividef(1.0f, 1.0f + __expf(-((Z0) + cvd[M])));         \
        float gm1 = __fdividef(1.0f, 1.0f + __expf(-((Z1) + cvd[M])));         \
        float hn0 = fmaf(gm0, hk0, qe0 * LGd[M]);                              \
        float hn1 = fmaf(gm1, hk1, qe1 * LGd[M]);                              \
        gob[dim * 32 + xo0] = hn0;                                             \
        gob[dim * 32 + xo1] = hn1;                                             \
        if (qn0 != 0.0f) atomicAdd(htn + dim, qn0 * hn0);                      \
        if (qn1 != 0.0f) atomicAdd(htn + dim, qn1 * hn1);                      \
    }
            EPI(C0[0], C0[1], 0)
            EPI(C0[2], C0[3], 1)
            EPI(C1[0], C1[1], 2)
            EPI(C1[2], C1[3], 3)
#undef EPI

            // last-finisher election issues the refill for u+RING
            if (lane == 0) {
                int old = atomicAdd(&sh_cnt[slot], 1);
                if ((old & 7) == 7) {
                    __threadfence();
                    const int un = u + RING;
                    if (un < total_u) ISSUE_U(un)
                }
            }
        }

        __threadfence();
        __syncthreads();
        if (tid == 0 && t < TSTEPS - 1) atomicAdd(&g_flag[b], 1);
    }
#undef ISSUE_U
}

// ---------------------------------------------------------------------------
__global__ void k_final(const int* __restrict__ e_data, const float* __restrict__ E_e,
                        const float* __restrict__ W5, const float* __restrict__ b5,
                        float* __restrict__ pred) {
    int b = blockIdx.x;
    int k = threadIdx.x;
    int tlast = S_ - 1;
    int en = e_data[b * S_ + tlast];
    const float* ee = E_e + en * DK_;
    const float* ht = g_ht + (tlast * B_ + b) * DK_;
    const float* w5k = W5 + k * (2 * DK_);
    float z = b5[k];
#pragma unroll
    for (int j = 0; j < DK_; j++) {
        z = fmaf(ee[j], w5k[j], z);
        z = fmaf(ht[j], w5k[DK_ + j], z);
    }
    float s = 1.0f / (1.0f + expf(-z));
#pragma unroll
    for (int off = 16; off; off >>= 1)
        s += __shfl_xor_sync(0xffffffffu, s, off);
    if (k == 0) pred[b * S_ + tlast] = s * (1.0f / DK_);
}

// ---------------------------------------------------------------------------
extern "C" void kernel_launch(void* const* d_in, const int* in_sizes, int n_in,
                              void* d_out, int out_size) {
    const int*   e_data  = (const int*)d_in[0];
    const int*   at_data = (const int*)d_in[1];
    const int*   it_data = (const int*)d_in[2];
    const float* a_data  = (const float*)d_in[3];
    const float* q       = (const float*)d_in[4];
    const float* E_e     = (const float*)d_in[5];
    const float* E_at    = (const float*)d_in[6];
    const float* E_it    = (const float*)d_in[7];
    const float* W1      = (const float*)d_in[8];
    const float* b1      = (const float*)d_in[9];
    const float* W2      = (const float*)d_in[10];
    const float* b2      = (const float*)d_in[11];
    const float* W3      = (const float*)d_in[12];
    const float* b3      = (const float*)d_in[13];
    const float* W4      = (const float*)d_in[14];
    const float* b4      = (const float*)d_in[15];
    const float* W5      = (const float*)d_in[16];
    const float* b5      = (const float*)d_in[17];
    const float* h0      = (const float*)d_in[18];
    float* pred = (float*)d_out;

    k_init<<<2048, 256>>>(h0, pred);
    k_embed<<<(S_ * B_ * DK_ + 255) / 256, 256>>>(e_data, at_data, it_data, a_data,
                                                  E_e, E_at, E_it, W1, b1);
    k_ht0<<<B_, 256>>>(e_data, q, h0);

    k_seq<<<NBLK, 256>>>(e_data, q, E_e, W2, b2, W3, b3, W4, b4, W5, b5, pred);

    k_final<<<B_, 32>>>(e_data, E_e, W5, b5, pred);
}

// round 16
// speedup vs baseline: 1.0005x; 1.0005x over previous
#include <cuda_runtime.h>

#define B_      64
#define S_      200
#define DK_     32
#define NQ1     4097
#define NMC     513           // 8-row microchunks per batch (4104 rows, 7 pad)
#define NBLK    296           // 148 SMs x 2 CTAs
#define TSTEPS  199

// g_h layout: [b][mc][k=32][r=8] — 1KB per microchunk, no swizzle.
static __device__ float g_h[(size_t)B_ * NMC * 256];
static __device__ float g_ht[S_ * B_ * DK_];
static __device__ float g_learn[S_ * B_ * DK_];
static __device__ float g_it[S_ * B_ * DK_];
static __device__ int   g_flag[B_];

typedef unsigned long long ull;

__device__ __forceinline__ unsigned smem_u32(const void* p) {
    unsigned a;
    asm("{ .reg .u64 t; cvta.to.shared.u64 t, %1; cvt.u32.u64 %0, t; }" : "=r"(a) : "l"(p));
    return a;
}
__device__ __forceinline__ void bulk_g2s(unsigned sdst, const void* gsrc, unsigned bytes,
                                         unsigned mbar) {
    asm volatile(
        "cp.async.bulk.shared::cta.global.mbarrier::complete_tx::bytes [%0], [%1], %2, [%3];"
        :: "r"(sdst), "l"(gsrc), "r"(bytes), "r"(mbar) : "memory");
}
__device__ __forceinline__ void mbar_wait(unsigned mbar, unsigned phase) {
    asm volatile(
        "{\n\t.reg .pred P;\n\t"
        "W_%=:\n\t"
        "mbarrier.try_wait.parity.shared.b64 P, [%0], %1, 0x989680;\n\t"
        "@P bra D_%=;\n\t"
        "bra.uni W_%=;\n\t"
        "D_%=:\n\t}"
        :: "r"(mbar), "r"(phase) : "memory");
}
__device__ __forceinline__ float tf32hi(float v) {
    return __uint_as_float(__float_as_uint(v) & 0xFFFFE000u);
}
__device__ __forceinline__ void mma8(float* c, const float* a, const float* b) {
    asm("mma.sync.aligned.m16n8k8.row.col.f32.tf32.tf32.f32 "
        "{%0,%1,%2,%3}, {%4,%5,%6,%7}, {%8,%9}, {%0,%1,%2,%3};"
        : "+f"(c[0]), "+f"(c[1]), "+f"(c[2]), "+f"(c[3])
        : "r"(__float_as_uint(a[0])), "r"(__float_as_uint(a[1])),
          "r"(__float_as_uint(a[2])), "r"(__float_as_uint(a[3])),
          "r"(__float_as_uint(b[0])), "r"(__float_as_uint(b[1])));
}

// ---------------------------------------------------------------------------
// K1: init g_h ([b][mc][k][r8], padding zeroed), zero h_tilde, flags, pred0
// ---------------------------------------------------------------------------
__global__ void k_init(const float* __restrict__ h0, float* __restrict__ pred) {
    const int PERB = NMC * 256;
    int stride = gridDim.x * blockDim.x;
    long total = (long)B_ * PERB;
    for (long i = blockIdx.x * blockDim.x + threadIdx.x; i < total; i += stride) {
        int b = (int)(i / PERB);
        int rem = (int)(i - (long)b * PERB);
        int mc = rem >> 8;
        int kk = (rem >> 3) & 31;
        int r = rem & 7;
        int grow = mc * 8 + r;
        g_h[i] = (grow < NQ1) ? h0[grow * DK_ + kk] : 0.0f;
    }
    int gid = blockIdx.x * blockDim.x + threadIdx.x;
    for (int i = gid; i < S_ * B_ * DK_; i += stride) g_ht[i] = 0.0f;
    if (gid < B_) { pred[gid * S_] = 0.0f; g_flag[gid] = 0; }
}

// ---------------------------------------------------------------------------
__global__ void k_embed(const int* __restrict__ e_data, const int* __restrict__ at_data,
                        const int* __restrict__ it_data, const float* __restrict__ a_data,
                        const float* __restrict__ E_e, const float* __restrict__ E_at,
                        const float* __restrict__ E_it,
                        const float* __restrict__ W1, const float* __restrict__ b1) {
    int idx = blockIdx.x * blockDim.x + threadIdx.x;
    if (idx >= S_ * B_ * DK_) return;
    int t = idx / (B_ * DK_);
    int rem = idx - t * (B_ * DK_);
    int b = rem >> 5;
    int k = rem & 31;
    int e  = e_data[b * S_ + t];
    int at = at_data[b * S_ + t];
    int it = it_data[b * S_ + t];
    float a = a_data[b * S_ + t];
    const float* ee  = E_e  + e  * DK_;
    const float* eat = E_at + at * DK_;
    const float* w1k = W1 + k * (3 * DK_);
    float s = b1[k];
    float ws = 0.0f;
#pragma unroll
    for (int j = 0; j < DK_; j++) {
        s = fmaf(ee[j],  w1k[j],       s);
        s = fmaf(eat[j], w1k[DK_ + j], s);
        ws += w1k[2 * DK_ + j];
    }
    s = fmaf(a, ws, s);
    g_learn[(t * B_ + b) * DK_ + k] = s;
    g_it[(t * B_ + b) * DK_ + k]    = E_it[it * DK_ + k];
}

// ---------------------------------------------------------------------------
__global__ void k_ht0(const int* __restrict__ e_data, const float* __restrict__ q,
                      const float* __restrict__ h0) {
    int b = blockIdx.x;
    int w = threadIdx.x >> 5;
    int lane = threadIdx.x & 31;
    const float* qr = q + (long)e_data[b * S_] * NQ1;
    float acc = 0.0f;
    for (int n = w; n < NQ1; n += 8) {
        float qv = qr[n];
        if (qv != 0.0f) acc = fmaf(qv, h0[n * DK_ + lane], acc);
    }
    atomicAdd(&g_ht[b * DK_ + lane], acc);
}

// ---------------------------------------------------------------------------
// k_seq: persistent, 296 blocks, 256 thr, 2 CTAs/SM. Each WARP owns a private
// 3-slot TMA ring over its own 8-row microchunks: wait own mbar -> 24 tf32
// mma -> float2 epilogue -> refill own slot. Zero cross-warp coordination
// inside a step; block syncs only at gate/prologue/step-end.
// ---------------------------------------------------------------------------
__global__ void __launch_bounds__(256, 2)
k_seq(const int* __restrict__ e_data, const float* __restrict__ q,
      const float* __restrict__ E_e,
      const float* __restrict__ W2, const float* __restrict__ b2,
      const float* __restrict__ W3, const float* __restrict__ b3,
      const float* __restrict__ W4, const float* __restrict__ b4,
      const float* __restrict__ W5, const float* __restrict__ b5,
      float* __restrict__ pred) {
    __shared__ __align__(16) float sh_h[8][3][256];   // 24KB: per-warp rings
    __shared__ __align__(16) float sh_q[8][3][32];    // 3KB: [0:16) qe, [16:32) qn
    __shared__ __align__(8)  ull   sh_mbar[24];
    __shared__ float sh_x[4 * DK_];
    __shared__ float sh_LG[DK_];
    __shared__ float sh_cv[DK_];
    __shared__ float sh_gl[DK_];
    __shared__ float sh_cB[DK_];

    const int g = blockIdx.x;
    const int tid = threadIdx.x;
    const int w = tid >> 5;
    const int lane = tid & 31;
    const int g2 = lane >> 2;
    const int tg = lane & 3;

    int b, ib, nb;
    if (g < 200) { b = g / 5; ib = g - b * 5; nb = 5; }
    else { int h2 = g - 200; int bb = h2 >> 2; b = 40 + bb; ib = h2 & 3; nb = 4; }
    const int mclo = (ib * NMC) / nb;
    const int mchi = ((ib + 1) * NMC) / nb;
    const int span = mchi - mclo;
    const int wmlo = mclo + (w * span) / 8;
    const int wmhi = mclo + ((w + 1) * span) / 8;
    const int nchw = wmhi - wmlo;          // 12..17 per warp

    const unsigned mbw = smem_u32(&sh_mbar[w * 3]);

    if (tid == 0) {
#pragma unroll
        for (int s = 0; s < 24; s++)
            asm volatile("mbarrier.init.shared.b64 [%0], 1;"
                         :: "r"(smem_u32(&sh_mbar[s])));
        asm volatile("fence.proxy.async.shared::cta;" ::: "memory");
    }
    __syncthreads();

// per-warp issue: step IT, warp-iter II, ring slot SL (lane0 only)
#define ISSUE(IT, II, SL)                                                               \
    {                                                                                   \
        int mc_ = wmlo + (II);                                                          \
        int et_ = e_data[b * S_ + (IT)];                                                \
        int en_ = e_data[b * S_ + (IT) + 1];                                            \
        ull pe = (ull)(q + (long)et_ * NQ1 + mc_ * 8);                                  \
        ull pn = (ull)(q + (long)en_ * NQ1 + mc_ * 8);                                  \
        unsigned qeb = ((32u + (unsigned)(pe & 15)) + 15) & ~15u;                       \
        unsigned qnb = ((32u + (unsigned)(pn & 15)) + 15) & ~15u;                       \
        unsigned mb = mbw + (SL) * 8;                                                   \
        asm volatile("mbarrier.arrive.expect_tx.shared.b64 _, [%0], %1;"                \
                     :: "r"(mb), "r"(1024u + qeb + qnb) : "memory");                    \
        bulk_g2s(smem_u32(&sh_h[w][SL][0]), g_h + ((size_t)b * NMC + mc_) * 256,        \
                 1024u, mb);                                                            \
        bulk_g2s(smem_u32(&sh_q[w][SL][0]),  (const void*)(pe & ~15ULL), qeb, mb);      \
        bulk_g2s(smem_u32(&sh_q[w][SL][16]), (const void*)(pn & ~15ULL), qnb, mb);      \
    }

    // ---- W4h fragments (hi/lo), loaded once ----
    float ah[2][4][4], al[2][4][4];
#pragma unroll
    for (int mt = 0; mt < 2; mt++)
#pragma unroll
        for (int kt = 0; kt < 4; kt++) {
            int d0 = g2 + 16 * mt, d1 = d0 + 8;
            int k0 = 8 * kt + tg,  k1 = k0 + 4;
            float v0 = W4[d0 * 96 + k0];
            float v1 = W4[d1 * 96 + k0];
            float v2 = W4[d0 * 96 + k1];
            float v3 = W4[d1 * 96 + k1];
            ah[mt][kt][0] = tf32hi(v0); al[mt][kt][0] = v0 - ah[mt][kt][0];
            ah[mt][kt][1] = tf32hi(v1); al[mt][kt][1] = v1 - ah[mt][kt][1];
            ah[mt][kt][2] = tf32hi(v2); al[mt][kt][2] = v2 - ah[mt][kt][2];
            ah[mt][kt][3] = tf32hi(v3); al[mt][kt][3] = v3 - ah[mt][kt][3];
        }

    // per-warp issue/consume cursors (uniform across lanes)
    int nt = 0, ni = 0;          // next issue (step, warp-iter)
#pragma unroll
    for (int j = 0; j < 3; j++) {
        if (lane == 0) ISSUE(nt, ni, j)
        ni++;                    // nchw >= 12, stays in step 0
    }
    int cs = 0, cph = 0;         // consume slot / phase

    for (int t = 0; t < TSTEPS; t++) {
        if (t > 0) {
            if (tid == 0) {
                int need = nb * t;
                int v;
                do {
                    asm volatile("ld.global.acquire.gpu.b32 %0, [%1];"
                                 : "=r"(v) : "l"(&g_flag[b]));
                } while (v < need);
            }
            __syncthreads();
        }

        const int e_t = e_data[b * S_ + t];
        const int e_n = e_data[b * S_ + t + 1];

        // ---- prologue: warps 0 (lg), 1 (gl), 2 (cB); warp 3 y-pred ----
        if (w < 3) {
            if (w == 0) {
                sh_x[lane]           = (t == 0) ? 0.0f : g_learn[((t - 1) * B_ + b) * DK_ + lane];
                sh_x[DK_ + lane]     = g_it[(t * B_ + b) * DK_ + lane];
                sh_x[2 * DK_ + lane] = g_learn[(t * B_ + b) * DK_ + lane];
                sh_x[3 * DK_ + lane] = g_ht[(t * B_ + b) * DK_ + lane];
            }
            asm volatile("bar.sync 7, 96;" ::: "memory");
            float lg = 0.0f;
            if (w == 0) {
                const float4* wk = (const float4*)(W2 + lane * 128);
                const float4* xv4 = (const float4*)sh_x;
                float a0 = b2[lane], a1 = 0.f, a2 = 0.f, a3 = 0.f;
#pragma unroll
                for (int j = 0; j < 32; j++) {
                    float4 xv = xv4[j]; float4 wa = wk[j];
                    a0 = fmaf(xv.x, wa.x, a0); a1 = fmaf(xv.y, wa.y, a1);
                    a2 = fmaf(xv.z, wa.z, a2); a3 = fmaf(xv.w, wa.w, a3);
                }
                lg = (a0 + a1) + (a2 + a3);
            } else if (w == 1) {
                const float4* wk = (const float4*)(W3 + lane * 128);
                const float4* xv4 = (const float4*)sh_x;
                float a0 = b3[lane], a1 = 0.f, a2 = 0.f, a3 = 0.f;
#pragma unroll
                for (int j = 0; j < 32; j++) {
                    float4 xv = xv4[j]; float4 wa = wk[j];
                    a0 = fmaf(xv.x, wa.x, a0); a1 = fmaf(xv.y, wa.y, a1);
                    a2 = fmaf(xv.z, wa.z, a2); a3 = fmaf(xv.w, wa.w, a3);
                }
                float gl = (a0 + a1) + (a2 + a3);
                sh_gl[lane] = 1.0f / (1.0f + expf(-gl));
            } else {
                const float* wk = W4 + lane * (3 * DK_) + 2 * DK_;
                float a0 = b4[lane], a1 = 0.f;
#pragma unroll
                for (int j = 0; j < DK_; j += 2) {
                    a0 = fmaf(sh_x[DK_ + j],     wk[j],     a0);
                    a1 = fmaf(sh_x[DK_ + j + 1], wk[j + 1], a1);
                }
                sh_cB[lane] = a0 + a1;
            }
            asm volatile("bar.sync 7, 96;" ::: "memory");
            if (w == 0) {
                lg = tanhf(lg);
                sh_LG[lane] = sh_gl[lane] * (lg + 1.0f) * 0.5f;
                __syncwarp();
                const float* w4l = W4 + lane * (3 * DK_) + DK_;
                float c0 = sh_cB[lane], c1 = 0.f;
#pragma unroll
                for (int j = 0; j < DK_; j += 2) {
                    c0 = fmaf(sh_LG[j],     w4l[j],     c0);
                    c1 = fmaf(sh_LG[j + 1], w4l[j + 1], c1);
                }
                sh_cv[lane] = c0 + c1;
            }
        } else if (w == 3 && ib == 0 && t > 0) {
            const float* ee = E_e + e_t * DK_;
            const float* ht = g_ht + (t * B_ + b) * DK_;
            const float* w5k = W5 + lane * (2 * DK_);
            float z = b5[lane];
#pragma unroll
            for (int j = 0; j < DK_; j++) {
                z = fmaf(ee[j], w5k[j], z);
                z = fmaf(ht[j], w5k[DK_ + j], z);
            }
            float s = 1.0f / (1.0f + expf(-z));
#pragma unroll
            for (int off = 16; off; off >>= 1)
                s += __shfl_xor_sync(0xffffffffu, s, off);
            if (lane == 0) pred[b * S_ + t] = s * (1.0f / DK_);
        }
        __syncthreads();

        float cvd[4], LGd[4];
#pragma unroll
        for (int m = 0; m < 4; m++) {
            cvd[m] = sh_cv[g2 + 8 * m];
            LGd[m] = sh_LG[g2 + 8 * m];
        }
        float* htn = g_ht + ((t + 1) * B_ + b) * DK_;
        const int qo_e = e_t & 3;      // (e*4097 + mc*8) mod 4 == e mod 4
        const int qo_n = e_n & 3;

        for (int i = 0; i < nchw; i++) {
            mbar_wait(mbw + cs * 8, cph);

            const int mc = wmlo + i;
            const float* tile = sh_h[w][cs];
            const float* sq = sh_q[w][cs];

            // ---- B frags (conflict-free LDS) + 3-term tf32 mma ----
            float bh[4][2], bl[4][2];
#pragma unroll
            for (int kt = 0; kt < 4; kt++) {
                int k0 = 8 * kt + tg;
                float v0 = tile[k0 * 8 + g2];
                float v1 = tile[(k0 + 4) * 8 + g2];
                bh[kt][0] = tf32hi(v0); bl[kt][0] = v0 - bh[kt][0];
                bh[kt][1] = tf32hi(v1); bl[kt][1] = v1 - bh[kt][1];
            }
            float C0[4] = {0.f, 0.f, 0.f, 0.f};
            float C1[4] = {0.f, 0.f, 0.f, 0.f};
#pragma unroll
            for (int kt = 0; kt < 4; kt++) {
                mma8(C0, ah[0][kt], bh[kt]);
                mma8(C1, ah[1][kt], bh[kt]);
            }
#pragma unroll
            for (int kt = 0; kt < 4; kt++) {
                mma8(C0, ah[0][kt], bl[kt]);
                mma8(C1, ah[1][kt], bl[kt]);
            }
#pragma unroll
            for (int kt = 0; kt < 4; kt++) {
                mma8(C0, al[0][kt], bh[kt]);
                mma8(C1, al[1][kt], bh[kt]);
            }

            // ---- epilogue: this thread's 2 rows (2tg, 2tg+1) x 4 dims ----
            const int row0 = mc * 8 + 2 * tg;
            const bool v0ok = row0 < NQ1;
            const bool v1ok = (row0 + 1) < NQ1;
            const float qe0 = v0ok ? sq[qo_e + 2 * tg]      : 0.0f;
            const float qe1 = v1ok ? sq[qo_e + 2 * tg + 1]  : 0.0f;
            const float qn0 = v0ok ? sq[16 + qo_n + 2 * tg]     : 0.0f;
            const float qn1 = v1ok ? sq[16 + qo_n + 2 * tg + 1] : 0.0f;
            float2* gob = (float2*)(g_h + ((size_t)b * NMC + mc) * 256);
            const float2* t2 = (const float2*)tile;

#define EPI(Z0, Z1, M)                                                         \
    {                                                                          \
        const int dim = g2 + 8 * (M);                                          \
        float2 hk = t2[dim * 4 + tg];                                          \
        float gm0 = __fdividef(1.0f, 1.0f + __expf(-((Z0) + cvd[M])));         \
        float gm1 = __fdividef(1.0f, 1.0f + __expf(-((Z1) + cvd[M])));         \
        float2 hn;                                                             \
        hn.x = fmaf(gm0, hk.x, qe0 * LGd[M]);                                  \
        hn.y = fmaf(gm1, hk.y, qe1 * LGd[M]);                                  \
        gob[dim * 4 + tg] = hn;                                                \
        if (qn0 != 0.0f) atomicAdd(htn + dim, qn0 * hn.x);                     \
        if (qn1 != 0.0f) atomicAdd(htn + dim, qn1 * hn.y);                     \
    }
            EPI(C0[0], C0[1], 0)
            EPI(C0[2], C0[3], 1)
            EPI(C1[0], C1[1], 2)
            EPI(C1[2], C1[3], 3)
#undef EPI

            // ---- refill own slot for iteration u+3 (no cross-warp wait) ----
            asm volatile("fence.proxy.async;" ::: "memory");
            if (lane == 0 && nt < TSTEPS) ISSUE(nt, ni, cs)
            ni++; if (ni == nchw) { ni = 0; nt++; }
            cs++; if (cs == 3) { cs = 0; cph ^= 1; }
        }

        __threadfence();
        __syncthreads();
        if (tid == 0 && t < TSTEPS - 1) atomicAdd(&g_flag[b], 1);
    }
#undef ISSUE
}

// ---------------------------------------------------------------------------
__global__ void k_final(const int* __restrict__ e_data, const float* __restrict__ E_e,
                        const float* __restrict__ W5, const float* __restrict__ b5,
                        float* __restrict__ pred) {
    int b = blockIdx.x;
    int k = threadIdx.x;
    int tlast = S_ - 1;
    int en = e_data[b * S_ + tlast];
    const float* ee = E_e + en * DK_;
    const float* ht = g_ht + (tlast * B_ + b) * DK_;
    const float* w5k = W5 + k * (2 * DK_);
    float z = b5[k];
#pragma unroll
    for (int j = 0; j < DK_; j++) {
        z = fmaf(ee[j], w5k[j], z);
        z = fmaf(ht[j], w5k[DK_ + j], z);
    }
    float s = 1.0f / (1.0f + expf(-z));
#pragma unroll
    for (int off = 16; off; off >>= 1)
        s += __shfl_xor_sync(0xffffffffu, s, off);
    if (k == 0) pred[b * S_ + tlast] = s * (1.0f / DK_);
}

// ---------------------------------------------------------------------------
extern "C" void kernel_launch(void* const* d_in, const int* in_sizes, int n_in,
                              void* d_out, int out_size) {
    const int*   e_data  = (const int*)d_in[0];
    const int*   at_data = (const int*)d_in[1];
    const int*   it_data = (const int*)d_in[2];
    const float* a_data  = (const float*)d_in[3];
    const float* q       = (const float*)d_in[4];
    const float* E_e     = (const float*)d_in[5];
    const float* E_at    = (const float*)d_in[6];
    const float* E_it    = (const float*)d_in[7];
    const float* W1      = (const float*)d_in[8];
    const float* b1      = (const float*)d_in[9];
    const float* W2      = (const float*)d_in[10];
    const float* b2      = (const float*)d_in[11];
    const float* W3      = (const float*)d_in[12];
    const float* b3      = (const float*)d_in[13];
    const float* W4      = (const float*)d_in[14];
    const float* b4      = (const float*)d_in[15];
    const float* W5      = (const float*)d_in[16];
    const float* b5      = (const float*)d_in[17];
    const float* h0      = (const float*)d_in[18];
    float* pred = (float*)d_out;

    k_init<<<2048, 256>>>(h0, pred);
    k_embed<<<(S_ * B_ * DK_ + 255) / 256, 256>>>(e_data, at_data, it_data, a_data,
                                                  E_e, E_at, E_it, W1, b1);
    k_ht0<<<B_, 256>>>(e_data, q, h0);

    k_seq<<<NBLK, 256>>>(e_data, q, E_e, W2, b2, W3, b3, W4, b4, W5, b5, pred);

    k_final<<<B_, 32>>>(e_data, E_e, W5, b5, pred);
}